// round 6
// baseline (speedup 1.0000x reference)
#include <cuda_runtime.h>
#include <math.h>
#include <stdint.h>

// Problem constants
#define BB 4
#define TT 2048
#define INF_ 64
#define DD 512
#define HH 8
#define DH 64
#define FF_ 2048
#define LL 4
#define LAT 128
#define PAST 40
#define FUT 120
#define ROWS (BB*TT)          // 8192
#define EPS 1e-5f

// ---------------- scratch (device globals; no allocation allowed) ----------
__device__ float g_x   [ROWS * DD];
__device__ float g_qkv [ROWS * 3 * DD];
__device__ float g_ctx [ROWS * DD];
__device__ float g_tmp [ROWS * DD];
__device__ float g_ff  [ROWS * FF_];
__device__ float g_pool[BB * DD];
__device__ float g_pp  [BB * 32 * DD];
__device__ float g_h   [BB * 2 * LAT];

// ---------------- helpers ---------------------------------------------------
__device__ __forceinline__ float f2tf(float x) {
    uint32_t u;
    asm("cvt.rna.tf32.f32 %0, %1;" : "=r"(u) : "f"(x));
    return __uint_as_float(u);
}
__device__ __forceinline__ uint32_t f2tfu(float x) {
    uint32_t u;
    asm("cvt.rna.tf32.f32 %0, %1;" : "=r"(u) : "f"(x));
    return u;
}
__device__ __forceinline__ uint32_t sptr(const void* p) {
    return (uint32_t)__cvta_generic_to_shared(p);
}
__device__ __forceinline__ void cpa16(uint32_t dst, const void* src) {
    asm volatile("cp.async.cg.shared.global [%0], [%1], 16;\n" :: "r"(dst), "l"(src));
}
#define CP_COMMIT() asm volatile("cp.async.commit_group;\n")
#define CP_WAIT(n)  asm volatile("cp.async.wait_group %0;\n" :: "n"(n))

#define MMA_TF32(d0,d1,d2,d3,a0,a1,a2,a3,b0,b1)                              \
    asm volatile("mma.sync.aligned.m16n8k8.row.col.f32.tf32.tf32.f32 "       \
        "{%0,%1,%2,%3},{%4,%5,%6,%7},{%8,%9},{%0,%1,%2,%3};"                 \
        : "+f"(d0),"+f"(d1),"+f"(d2),"+f"(d3)                                \
        : "r"(a0),"r"(a1),"r"(a2),"r"(a3),"r"(b0),"r"(b1))

// ---------------- TF32 tensor-core GEMM, 3-stage cp.async pipeline ----------
// EPI: 0 = +bias ; 1 = +bias, relu ; 2 = +bias + pos_enc[row%T]
#define GEMM_APAD 20
#define GEMM_BPAD 136
#define GEMM_ASZ  (128 * GEMM_APAD)
#define GEMM_BSZ  (16 * GEMM_BPAD)
#define GEMM_SMEM (3 * (GEMM_ASZ + GEMM_BSZ) * 4)   // 56832 B

template <int EPI>
__global__ __launch_bounds__(256)
void gemm_tf32(const float* __restrict__ A, const float* __restrict__ B,
               const float* __restrict__ bias, const float* __restrict__ extra,
               float* __restrict__ C, int M, int N, int K)
{
    constexpr int BM = 128, BN = 128, BK = 16;
    extern __shared__ float sm[];
    float* As = sm;
    float* Bs = sm + 3 * GEMM_ASZ;

    const int tid  = threadIdx.x;
    const int wid  = tid >> 5, lane = tid & 31;
    const int g    = lane >> 2, c = lane & 3;
    const int wm   = (wid >> 2) * 64;
    const int wn   = (wid & 3) * 32;
    const int brow = blockIdx.y * BM, bcol = blockIdx.x * BN;

    const int arow = tid >> 1,  acol = (tid & 1) * 8;
    const int brw  = tid >> 4,  bcl  = (tid & 15) * 8;

    const float* Ag = A + (size_t)(brow + arow) * K + acol;
    const float* Bg = B + bcol + bcl;

    const uint32_t sA = sptr(As) + (uint32_t)(arow * GEMM_APAD + acol) * 4u;
    const uint32_t sB = sptr(Bs) + (uint32_t)(brw * GEMM_BPAD + bcl) * 4u;

    float acc[4][4][4];
#pragma unroll
    for (int i = 0; i < 4; i++)
#pragma unroll
        for (int j = 0; j < 4; j++)
#pragma unroll
            for (int r = 0; r < 4; r++) acc[i][j][r] = 0.f;

    const int nk = K / BK;

    {
        cpa16(sA, Ag);       cpa16(sA + 16, Ag + 4);
        cpa16(sB, Bg + (size_t)brw * N);
        cpa16(sB + 16, Bg + (size_t)brw * N + 4);
        CP_COMMIT();
        if (nk > 1) {
            cpa16(sA + GEMM_ASZ * 4, Ag + BK);
            cpa16(sA + GEMM_ASZ * 4 + 16, Ag + BK + 4);
            cpa16(sB + GEMM_BSZ * 4, Bg + (size_t)(BK + brw) * N);
            cpa16(sB + GEMM_BSZ * 4 + 16, Bg + (size_t)(BK + brw) * N + 4);
            CP_COMMIT();
            CP_WAIT(1);
        } else {
            CP_WAIT(0);
        }
        __syncthreads();
    }

    int s_cur = 0;
    for (int k0 = 0; k0 < nk; k0++) {
        if (k0 + 2 < nk) {
            const int s = (s_cur + 2 >= 3) ? s_cur - 1 : s_cur + 2;
            const float* ga = Ag + (k0 + 2) * BK;
            cpa16(sA + s * GEMM_ASZ * 4, ga);
            cpa16(sA + s * GEMM_ASZ * 4 + 16, ga + 4);
            const float* gb = Bg + (size_t)((k0 + 2) * BK + brw) * N;
            cpa16(sB + s * GEMM_BSZ * 4, gb);
            cpa16(sB + s * GEMM_BSZ * 4 + 16, gb + 4);
            CP_COMMIT();
        }

        const float* Ab = As + s_cur * GEMM_ASZ;
        const float* Bb = Bs + s_cur * GEMM_BSZ;
#pragma unroll
        for (int kk = 0; kk < 2; kk++) {
            uint32_t af[4][4];
#pragma unroll
            for (int mt = 0; mt < 4; mt++) {
                const int m0 = wm + mt * 16 + g;
                af[mt][0] = f2tfu(Ab[(m0    ) * GEMM_APAD + kk * 8 + c    ]);
                af[mt][1] = f2tfu(Ab[(m0 + 8) * GEMM_APAD + kk * 8 + c    ]);
                af[mt][2] = f2tfu(Ab[(m0    ) * GEMM_APAD + kk * 8 + c + 4]);
                af[mt][3] = f2tfu(Ab[(m0 + 8) * GEMM_APAD + kk * 8 + c + 4]);
            }
            uint32_t bf[4][2];
#pragma unroll
            for (int nt = 0; nt < 4; nt++) {
                const int n0 = wn + nt * 8 + g;
                bf[nt][0] = f2tfu(Bb[(kk * 8 + c    ) * GEMM_BPAD + n0]);
                bf[nt][1] = f2tfu(Bb[(kk * 8 + c + 4) * GEMM_BPAD + n0]);
            }
#pragma unroll
            for (int mt = 0; mt < 4; mt++)
#pragma unroll
                for (int nt = 0; nt < 4; nt++)
                    MMA_TF32(acc[mt][nt][0], acc[mt][nt][1], acc[mt][nt][2], acc[mt][nt][3],
                             af[mt][0], af[mt][1], af[mt][2], af[mt][3],
                             bf[nt][0], bf[nt][1]);
        }

        if (k0 + 1 < nk) {
            if (k0 + 2 < nk) CP_WAIT(1); else CP_WAIT(0);
            __syncthreads();
        }
        s_cur = (s_cur + 1 >= 3) ? 0 : s_cur + 1;
    }

#pragma unroll
    for (int mt = 0; mt < 4; mt++) {
#pragma unroll
        for (int nt = 0; nt < 4; nt++) {
            const int col = bcol + wn + nt * 8 + 2 * c;
            const float b0 = bias[col], b1 = bias[col + 1];
#pragma unroll
            for (int half = 0; half < 2; half++) {
                const int row = brow + wm + mt * 16 + g + half * 8;
                float v0 = acc[mt][nt][half * 2 + 0] + b0;
                float v1 = acc[mt][nt][half * 2 + 1] + b1;
                if (EPI == 1) { v0 = fmaxf(v0, 0.f); v1 = fmaxf(v1, 0.f); }
                if (EPI == 2) {
                    const int t = row & (TT - 1);
                    v0 += extra[(size_t)t * N + col];
                    v1 += extra[(size_t)t * N + col + 1];
                }
                float2 o; o.x = v0; o.y = v1;
                *(float2*)(C + (size_t)row * N + col) = o;
            }
        }
    }
}

// ---------------- banded flash attention v2 ---------------------------------
// Block: 128 queries of one (b,h). 8 warps, 16 query rows each.
// Key window: up to 5 aligned 64-key chunks {q0-64, q0, q0+64, q0+128, q0+192}.
// P never touches smem: PV A-fragments built from softmax accumulators via shfl.
// Per-warp fully-masked key-group skipping.
#define KVP 72
#define ABUF (64 * KVP)
#define ATTN_SMEM (4 * ABUF * 4)   // Ks[2] + Vs[2] = 73728 B

__global__ __launch_bounds__(256, 2)
void attn_mma(const float* __restrict__ qkv, float* __restrict__ ctx)
{
    extern __shared__ float sm[];
    float* Ks = sm;                 // [2][64][72]
    float* Vs = sm + 2 * ABUF;      // [2][64][72]

    const int blk = blockIdx.x;
    const int qt = blk & 15;
    const int h  = (blk >> 4) & 7;
    const int b  = blk >> 7;
    const int q0 = qt * 128;

    const int tid = threadIdx.x, wid = tid >> 5, lane = tid & 31;
    const int g = lane >> 2, c = lane & 3;
    const int w0 = q0 + wid * 16;            // warp's first query row
    const int r0 = w0 + g, r1 = r0 + 8;

    // ---- Q fragments (tf32)
    uint32_t qa[8][4];
#pragma unroll
    for (int kt = 0; kt < 8; kt++) {
        const float* q_lo = qkv + (size_t)(b * TT + r0) * 1536 + h * 64 + kt * 8;
        const float* q_hi = qkv + (size_t)(b * TT + r1) * 1536 + h * 64 + kt * 8;
        qa[kt][0] = f2tfu(q_lo[c]);
        qa[kt][1] = f2tfu(q_hi[c]);
        qa[kt][2] = f2tfu(q_lo[c + 4]);
        qa[kt][3] = f2tfu(q_hi[c + 4]);
    }

    float oacc[8][4];
#pragma unroll
    for (int nt = 0; nt < 8; nt++)
#pragma unroll
        for (int e = 0; e < 4; e++) oacc[nt][e] = 0.f;

    float m0 = -INFINITY, m1 = -INFINITY, l0 = 0.f, l1 = 0.f;
    const float scale = 0.125f;

    // chunk list (any order is numerically safe via fmax guards)
    int csv[5]; int ncs = 0;
    const int offs[5] = {-64, 0, 64, 128, 192};
#pragma unroll
    for (int i = 0; i < 5; i++) {
        const int cs = q0 + offs[i];
        if (cs >= 0 && cs < TT) csv[ncs++] = cs;
    }

    // loader: 256 threads; tid>>7 selects K/V, row = (tid>>1)&63, half = tid&1
    const int lrow  = (tid >> 1) & 63;
    const int isv   = tid >> 7;
    const int lhalf = tid & 1;
    const uint32_t ldst0 = sptr((isv ? Vs : Ks) + lrow * KVP + lhalf * 32);
    const size_t lsrc_off = (size_t)512 + (size_t)isv * 512 + h * 64 + lhalf * 32;

    {   // prologue: chunk 0
        const float* src = qkv + (size_t)(b * TT + csv[0] + lrow) * 1536 + lsrc_off;
#pragma unroll
        for (int i = 0; i < 8; i++) cpa16(ldst0 + i * 16, src + i * 4);
        CP_COMMIT();
    }

    // PV shuffle sources (constant per thread)
    const int srcA = (lane & 28) | (c >> 1);
    const int srcB = srcA + 2;
    const bool odd = (c & 1) != 0;

    for (int ci = 0; ci < ncs; ci++) {
        CP_WAIT(0);
        __syncthreads();

        if (ci + 1 < ncs) {
            const uint32_t dst = ldst0 + ((ci + 1) & 1) * ABUF * 4;
            const float* src = qkv + (size_t)(b * TT + csv[ci + 1] + lrow) * 1536 + lsrc_off;
#pragma unroll
            for (int i = 0; i < 8; i++) cpa16(dst + i * 16, src + i * 4);
            CP_COMMIT();
        }

        const int cs = csv[ci];
        // warp-valid key-group range within this chunk
        const int lo_key = max(cs, w0 - PAST);
        const int hi_key = min(cs + 63, w0 + 15 + FUT);
        if (lo_key > hi_key) continue;        // warp-uniform; next iter syncs
        const int ntlo = (lo_key - cs) >> 3;
        const int nthi = (hi_key - cs) >> 3;

        const float* Kb = Ks + (ci & 1) * ABUF;
        const float* Vb = Vs + (ci & 1) * ABUF;

        // ---- S = Q @ K^T for valid groups
        float sacc[8][4];
#pragma unroll
        for (int nt = 0; nt < 8; nt++) {
            sacc[nt][0] = 0.f; sacc[nt][1] = 0.f;
            sacc[nt][2] = 0.f; sacc[nt][3] = 0.f;
        }
#pragma unroll
        for (int nt = 0; nt < 8; nt++) {
            if (nt < ntlo || nt > nthi) continue;
#pragma unroll
            for (int kt = 0; kt < 8; kt++) {
                const uint32_t b0 = f2tfu(Kb[(nt * 8 + g) * KVP + kt * 8 + c]);
                const uint32_t b1 = f2tfu(Kb[(nt * 8 + g) * KVP + kt * 8 + c + 4]);
                MMA_TF32(sacc[nt][0], sacc[nt][1], sacc[nt][2], sacc[nt][3],
                         qa[kt][0], qa[kt][1], qa[kt][2], qa[kt][3], b0, b1);
            }
        }

        // ---- mask + row max over valid groups
        float mx0 = -INFINITY, mx1 = -INFINITY;
#pragma unroll
        for (int nt = 0; nt < 8; nt++) {
            if (nt < ntlo || nt > nthi) continue;
            const int j0 = cs + nt * 8 + 2 * c;
            const int j1 = j0 + 1;
            float v;
            v = sacc[nt][0] * scale;
            v = (j0 >= r0 - PAST && j0 <= r0 + FUT) ? v : -INFINITY;
            sacc[nt][0] = v; mx0 = fmaxf(mx0, v);
            v = sacc[nt][1] * scale;
            v = (j1 >= r0 - PAST && j1 <= r0 + FUT) ? v : -INFINITY;
            sacc[nt][1] = v; mx0 = fmaxf(mx0, v);
            v = sacc[nt][2] * scale;
            v = (j0 >= r1 - PAST && j0 <= r1 + FUT) ? v : -INFINITY;
            sacc[nt][2] = v; mx1 = fmaxf(mx1, v);
            v = sacc[nt][3] * scale;
            v = (j1 >= r1 - PAST && j1 <= r1 + FUT) ? v : -INFINITY;
            sacc[nt][3] = v; mx1 = fmaxf(mx1, v);
        }
        mx0 = fmaxf(mx0, __shfl_xor_sync(0xffffffffu, mx0, 1));
        mx0 = fmaxf(mx0, __shfl_xor_sync(0xffffffffu, mx0, 2));
        mx1 = fmaxf(mx1, __shfl_xor_sync(0xffffffffu, mx1, 1));
        mx1 = fmaxf(mx1, __shfl_xor_sync(0xffffffffu, mx1, 2));

        const float mn0 = fmaxf(m0, mx0);
        const float mn1 = fmaxf(m1, mx1);
        // fmax guard: (-inf) - (-inf) = nan -> fmaxf(nan, -88) = -88 -> exp ~ 0
        const float rf0 = __expf(fmaxf(m0 - mn0, -88.f));
        const float rf1 = __expf(fmaxf(m1 - mn1, -88.f));
        m0 = mn0; m1 = mn1;

        // ---- p = exp(s - m) in place (tf32-rounded), row sums
        float ps0 = 0.f, ps1 = 0.f;
#pragma unroll
        for (int nt = 0; nt < 8; nt++) {
            if (nt < ntlo || nt > nthi) continue;
            const float p00 = __expf(fmaxf(sacc[nt][0] - mn0, -88.f));
            const float p01 = __expf(fmaxf(sacc[nt][1] - mn0, -88.f));
            const float p10 = __expf(fmaxf(sacc[nt][2] - mn1, -88.f));
            const float p11 = __expf(fmaxf(sacc[nt][3] - mn1, -88.f));
            ps0 += p00 + p01;
            ps1 += p10 + p11;
            sacc[nt][0] = f2tf(p00);
            sacc[nt][1] = f2tf(p01);
            sacc[nt][2] = f2tf(p10);
            sacc[nt][3] = f2tf(p11);
        }
        ps0 += __shfl_xor_sync(0xffffffffu, ps0, 1);
        ps0 += __shfl_xor_sync(0xffffffffu, ps0, 2);
        ps1 += __shfl_xor_sync(0xffffffffu, ps1, 1);
        ps1 += __shfl_xor_sync(0xffffffffu, ps1, 2);
        l0 = l0 * rf0 + ps0;
        l1 = l1 * rf1 + ps1;

#pragma unroll
        for (int nt = 0; nt < 8; nt++) {
            oacc[nt][0] *= rf0; oacc[nt][1] *= rf0;
            oacc[nt][2] *= rf1; oacc[nt][3] *= rf1;
        }

        // ---- O += P @ V ; A-fragments built via shuffle from sacc
#pragma unroll
        for (int kt = 0; kt < 8; kt++) {
            if (kt < ntlo || kt > nthi) continue;
            float v00 = __shfl_sync(0xffffffffu, sacc[kt][0], srcA);
            float v01 = __shfl_sync(0xffffffffu, sacc[kt][1], srcA);
            float v10 = __shfl_sync(0xffffffffu, sacc[kt][2], srcA);
            float v11 = __shfl_sync(0xffffffffu, sacc[kt][3], srcA);
            const uint32_t a0 = __float_as_uint(odd ? v01 : v00);
            const uint32_t a1 = __float_as_uint(odd ? v11 : v10);
            v00 = __shfl_sync(0xffffffffu, sacc[kt][0], srcB);
            v01 = __shfl_sync(0xffffffffu, sacc[kt][1], srcB);
            v10 = __shfl_sync(0xffffffffu, sacc[kt][2], srcB);
            v11 = __shfl_sync(0xffffffffu, sacc[kt][3], srcB);
            const uint32_t a2 = __float_as_uint(odd ? v01 : v00);
            const uint32_t a3 = __float_as_uint(odd ? v11 : v10);
#pragma unroll
            for (int nt = 0; nt < 8; nt++) {
                const uint32_t b0 = f2tfu(Vb[(kt * 8 + c    ) * KVP + nt * 8 + g]);
                const uint32_t b1 = f2tfu(Vb[(kt * 8 + c + 4) * KVP + nt * 8 + g]);
                MMA_TF32(oacc[nt][0], oacc[nt][1], oacc[nt][2], oacc[nt][3],
                         a0, a1, a2, a3, b0, b1);
            }
        }
    }

    // ---- write O
    const float inv0 = 1.f / l0, inv1 = 1.f / l1;
#pragma unroll
    for (int nt = 0; nt < 8; nt++) {
        const int col = h * 64 + nt * 8 + 2 * c;
        float2 w;
        w.x = oacc[nt][0] * inv0; w.y = oacc[nt][1] * inv0;
        *(float2*)(ctx + (size_t)(b * TT + r0) * DD + col) = w;
        w.x = oacc[nt][2] * inv1; w.y = oacc[nt][3] * inv1;
        *(float2*)(ctx + (size_t)(b * TT + r1) * DD + col) = w;
    }
}

// ---------------- residual add + LayerNorm (row = 512) ---------------------
__global__ __launch_bounds__(128)
void add_ln(const float* __restrict__ x, const float* __restrict__ y,
            const float* __restrict__ s, const float* __restrict__ bta,
            float* __restrict__ out)
{
    const int row = blockIdx.x;
    const int tid = threadIdx.x;
    float v[4];
    float sum = 0.f, sq = 0.f;
#pragma unroll
    for (int i = 0; i < 4; i++) {
        int c = tid + i * 128;
        float val = x[(size_t)row * DD + c] + y[(size_t)row * DD + c];
        v[i] = val;
        sum += val;
        sq  += val * val;
    }
    __shared__ float rs[8];
#pragma unroll
    for (int off = 16; off > 0; off >>= 1) {
        sum += __shfl_xor_sync(0xffffffffu, sum, off);
        sq  += __shfl_xor_sync(0xffffffffu, sq,  off);
    }
    if ((tid & 31) == 0) { rs[tid >> 5] = sum; rs[4 + (tid >> 5)] = sq; }
    __syncthreads();
    sum = rs[0] + rs[1] + rs[2] + rs[3];
    sq  = rs[4] + rs[5] + rs[6] + rs[7];
    const float mean = sum * (1.f / DD);
    const float var  = sq * (1.f / DD) - mean * mean;
    const float inv  = rsqrtf(var + EPS);
#pragma unroll
    for (int i = 0; i < 4; i++) {
        int c = tid + i * 128;
        out[(size_t)row * DD + c] = (v[i] - mean) * inv * s[c] + bta[c];
    }
}

// ---------------- mean pool (two-stage) -------------------------------------
__global__ void pool_partial(const float* __restrict__ emb, float* __restrict__ pp)
{
    const int b = blockIdx.x >> 5, ch = blockIdx.x & 31;
    const int d = threadIdx.x;
    float s = 0.f;
    const int t0 = ch * 64;
    for (int t = t0; t < t0 + 64; t++)
        s += emb[((size_t)(b * TT + t)) * DD + d];
    pp[(size_t)blockIdx.x * DD + d] = s;
}

__global__ void pool_reduce(const float* __restrict__ pp, float* __restrict__ p)
{
    const int b = blockIdx.x, d = threadIdx.x;
    float s = 0.f;
    for (int ch = 0; ch < 32; ch++)
        s += pp[(size_t)(b * 32 + ch) * DD + d];
    p[b * DD + d] = s * (1.f / TT);
}

// ---------------- tiny dense layer (heads) ----------------------------------
__global__ void small_linear(const float* __restrict__ in, const float* __restrict__ W,
                             const float* __restrict__ bias, float* __restrict__ out,
                             int K, int N, int relu)
{
    const int b = blockIdx.x, n = threadIdx.x;
    if (n >= N) return;
    float sum = bias[n];
    for (int k = 0; k < K; k++)
        sum = fmaf(in[b * K + k], W[(size_t)k * N + n], sum);
    if (relu) sum = fmaxf(sum, 0.f);
    out[b * N + n] = sum;
}

// ---------------- launch -----------------------------------------------------
extern "C" void kernel_launch(void* const* d_in, const int* in_sizes, int n_in,
                              void* d_out, int out_size)
{
    const float* feats  = (const float*)d_in[0];
    const float* projW  = (const float*)d_in[1];
    const float* projB  = (const float*)d_in[2];
    const float* posenc = (const float*)d_in[3];
    const float* qkvW   = (const float*)d_in[4];
    const float* qkvB   = (const float*)d_in[5];
    const float* outW   = (const float*)d_in[6];
    const float* outB   = (const float*)d_in[7];
    const float* ln1s   = (const float*)d_in[8];
    const float* ln1b   = (const float*)d_in[9];
    const float* ff1W   = (const float*)d_in[10];
    const float* ff1B   = (const float*)d_in[11];
    const float* ff2W   = (const float*)d_in[12];
    const float* ff2B   = (const float*)d_in[13];
    const float* ln2s   = (const float*)d_in[14];
    const float* ln2b   = (const float*)d_in[15];
    const float* mu1W   = (const float*)d_in[16];
    const float* mu1B   = (const float*)d_in[17];
    const float* mu2W   = (const float*)d_in[18];
    const float* mu2B   = (const float*)d_in[19];
    const float* lv1W   = (const float*)d_in[20];
    const float* lv1B   = (const float*)d_in[21];
    const float* lv2W   = (const float*)d_in[22];
    const float* lv2B   = (const float*)d_in[23];

    float *px, *pqkv, *pctx, *ptmp, *pff, *ppool, *ppp, *ph;
    cudaGetSymbolAddress((void**)&px,    g_x);
    cudaGetSymbolAddress((void**)&pqkv,  g_qkv);
    cudaGetSymbolAddress((void**)&pctx,  g_ctx);
    cudaGetSymbolAddress((void**)&ptmp,  g_tmp);
    cudaGetSymbolAddress((void**)&pff,   g_ff);
    cudaGetSymbolAddress((void**)&ppool, g_pool);
    cudaGetSymbolAddress((void**)&ppp,   g_pp);
    cudaGetSymbolAddress((void**)&ph,    g_h);

    cudaFuncSetAttribute(gemm_tf32<0>, cudaFuncAttributeMaxDynamicSharedMemorySize, GEMM_SMEM);
    cudaFuncSetAttribute(gemm_tf32<1>, cudaFuncAttributeMaxDynamicSharedMemorySize, GEMM_SMEM);
    cudaFuncSetAttribute(gemm_tf32<2>, cudaFuncAttributeMaxDynamicSharedMemorySize, GEMM_SMEM);
    cudaFuncSetAttribute(attn_mma,     cudaFuncAttributeMaxDynamicSharedMemorySize, ATTN_SMEM);

    float* emb = (float*)d_out;
    float* mu  = emb + (size_t)ROWS * DD;
    float* lv  = mu + BB * LAT;

    // x = feats @ projW + projB + posenc
    {
        dim3 grid(DD / 128, ROWS / 128);
        gemm_tf32<2><<<grid, 256, GEMM_SMEM>>>(feats, projW, projB, posenc, px, ROWS, DD, INF_);
    }

    for (int l = 0; l < LL; l++) {
        {
            dim3 grid((3 * DD) / 128, ROWS / 128);
            gemm_tf32<0><<<grid, 256, GEMM_SMEM>>>(px, qkvW + (size_t)l * DD * 3 * DD,
                                        qkvB + l * 3 * DD, nullptr, pqkv,
                                        ROWS, 3 * DD, DD);
        }
        attn_mma<<<BB * HH * 16, 256, ATTN_SMEM>>>(pqkv, pctx);
        {
            dim3 grid(DD / 128, ROWS / 128);
            gemm_tf32<0><<<grid, 256, GEMM_SMEM>>>(pctx, outW + (size_t)l * DD * DD,
                                        outB + l * DD, nullptr, ptmp, ROWS, DD, DD);
        }
        add_ln<<<ROWS, 128>>>(px, ptmp, ln1s + l * DD, ln1b + l * DD, px);
        {
            dim3 grid(FF_ / 128, ROWS / 128);
            gemm_tf32<1><<<grid, 256, GEMM_SMEM>>>(px, ff1W + (size_t)l * DD * FF_,
                                        ff1B + l * FF_, nullptr, pff, ROWS, FF_, DD);
        }
        {
            dim3 grid(DD / 128, ROWS / 128);
            gemm_tf32<0><<<grid, 256, GEMM_SMEM>>>(pff, ff2W + (size_t)l * FF_ * DD,
                                        ff2B + l * DD, nullptr, ptmp, ROWS, DD, FF_);
        }
        float* dst = (l == LL - 1) ? emb : px;
        add_ln<<<ROWS, 128>>>(px, ptmp, ln2s + l * DD, ln2b + l * DD, dst);
    }

    pool_partial<<<BB * 32, DD>>>(emb, ppp);
    pool_reduce<<<BB, DD>>>(ppp, ppool);
    small_linear<<<BB, 2 * LAT>>>(ppool, mu1W, mu1B, ph, DD, 2 * LAT, 1);
    small_linear<<<BB, LAT>>>(ph, mu2W, mu2B, mu, 2 * LAT, LAT, 0);
    small_linear<<<BB, 2 * LAT>>>(ppool, lv1W, lv1B, ph, DD, 2 * LAT, 1);
    small_linear<<<BB, LAT>>>(ph, lv2W, lv2B, lv, 2 * LAT, LAT, 0);
}